// round 6
// baseline (speedup 1.0000x reference)
#include <cuda_runtime.h>
#include <cuda_fp16.h>
#include <cstdint>

#define B_   2
#define S_   2048
#define E_   1024
#define H_   16
#define D_   64
#define WIN  3
#define MS_  (B_*S_)          // 4096 rows

typedef __half f16;

// Q scale folded with log2(e): exp(q.k/8) = exp2((q*QSCALE).k)
#define QSCALE 0.18033688011112042f   // 0.125 * log2(e)

// ---------------------------------------------------------------------------
// Device-global scratch (allocation-free)
// ---------------------------------------------------------------------------
__device__ f16 g_x[MS_*E_];
__device__ f16 g_wq[E_*E_], g_wk[E_*E_], g_wv[E_*E_];
__device__ f16 g_qh[B_*H_*S_*D_];
__device__ f16 g_kh[B_*H_*S_*D_];
__device__ f16 g_vh[B_*H_*S_*D_];

// ---------------------------------------------------------------------------
// Helpers
// ---------------------------------------------------------------------------
__device__ __forceinline__ uint32_t smem_u32(const void* p) {
    uint32_t a;
    asm("{ .reg .u64 t; cvta.to.shared.u64 t, %1; cvt.u32.u64 %0, t; }"
        : "=r"(a) : "l"(p));
    return a;
}
__device__ __forceinline__ void cp16(uint32_t dst, const void* src) {
    asm volatile("cp.async.cg.shared.global [%0], [%1], 16;"
                 :: "r"(dst), "l"(src) : "memory");
}
__device__ __forceinline__ void cp_commit() {
    asm volatile("cp.async.commit_group;" ::: "memory");
}
template <int N>
__device__ __forceinline__ void cp_wait() {
    asm volatile("cp.async.wait_group %0;" :: "n"(N) : "memory");
}
__device__ __forceinline__ void ldsm4(uint32_t* r, uint32_t addr) {
    asm volatile("ldmatrix.sync.aligned.m8n8.x4.shared.b16 {%0,%1,%2,%3}, [%4];"
                 : "=r"(r[0]), "=r"(r[1]), "=r"(r[2]), "=r"(r[3]) : "r"(addr));
}
__device__ __forceinline__ void ldsm4t(uint32_t* r, uint32_t addr) {
    asm volatile("ldmatrix.sync.aligned.m8n8.x4.trans.shared.b16 {%0,%1,%2,%3}, [%4];"
                 : "=r"(r[0]), "=r"(r[1]), "=r"(r[2]), "=r"(r[3]) : "r"(addr));
}
__device__ __forceinline__ void mma16816(float* c, const uint32_t* a,
                                         uint32_t b0, uint32_t b1) {
    asm volatile(
        "mma.sync.aligned.m16n8k16.row.col.f32.f16.f16.f32 "
        "{%0,%1,%2,%3}, {%4,%5,%6,%7}, {%8,%9}, {%0,%1,%2,%3};"
        : "+f"(c[0]), "+f"(c[1]), "+f"(c[2]), "+f"(c[3])
        : "r"(a[0]), "r"(a[1]), "r"(a[2]), "r"(a[3]), "r"(b0), "r"(b1));
}
__device__ __forceinline__ uint32_t pack_h2(float x, float y) {
    __half2 h = __floats2half2_rn(x, y);
    return *reinterpret_cast<uint32_t*>(&h);
}
__device__ __forceinline__ float ex2(float x) {
    float r;
    asm("ex2.approx.ftz.f32 %0, %1;" : "=f"(r) : "f"(x));
    return r;
}

// ---------------------------------------------------------------------------
// Fused fp32->fp16 conversion for X, Wq, Wk, Wv (one launch)
// ---------------------------------------------------------------------------
#define NX4 (MS_*E_/4)     // 1048576
#define NW4 (E_*E_/4)      // 262144 = 2^18

__global__ __launch_bounds__(256) void cvt_all(
    const float* __restrict__ X,  const float* __restrict__ Wq,
    const float* __restrict__ Wk, const float* __restrict__ Wv)
{
    int i = blockIdx.x * 256 + threadIdx.x;
    const float* src;
    f16* dst;
    int idx;
    if (i < NX4) {
        src = X; dst = g_x; idx = i;
    } else {
        int j = i - NX4;
        int t = j >> 18;
        idx = j & (NW4 - 1);
        src = (t == 0) ? Wq : (t == 1) ? Wk : Wv;
        dst = (t == 0) ? g_wq : (t == 1) ? g_wk : g_wv;
    }
    float4 v = ((const float4*)src)[idx];
    ((uint32_t*)dst)[idx * 2 + 0] = pack_h2(v.x, v.y);
    ((uint32_t*)dst)[idx * 2 + 1] = pack_h2(v.z, v.w);
}

// ---------------------------------------------------------------------------
// Fused projection GEMM (Q, K, V by blockIdx.z):
// CTA tile 128(M) x 64(N), K-chunk 32, 8 warps (2m x 4n), warp tile 64x16.
// smem: 2 stages x [A(128x80B), B(64x80B)] = 30720 B -> 2 CTAs/SM.
// ---------------------------------------------------------------------------
#define P_PITCH  80
#define PA_TILE  (128 * P_PITCH)       // 10240
#define PB_TILE  (64 * P_PITCH)        // 5120
#define P_STAGE  (PA_TILE + PB_TILE)   // 15360
#define P_SMEM   (2 * P_STAGE)         // 30720

__global__ __launch_bounds__(256, 2) void proj_fused(
    const f16* __restrict__ Wq_, const float* __restrict__ bq_,
    const f16* __restrict__ Wk_, const float* __restrict__ bk_,
    const f16* __restrict__ Wv_, const float* __restrict__ bv_,
    f16* __restrict__ Dq_, f16* __restrict__ Dk_, f16* __restrict__ Dv_)
{
    const int z = blockIdx.z;
    const f16*   W    = (z == 0) ? Wq_ : (z == 1) ? Wk_ : Wv_;
    const float* bias = (z == 0) ? bq_ : (z == 1) ? bk_ : bv_;
    f16*         Dst  = (z == 0) ? Dq_ : (z == 1) ? Dk_ : Dv_;
    const float scale = (z == 0) ? QSCALE : 1.0f;

    extern __shared__ char sm[];
    const uint32_t smb = smem_u32(sm);
    const int tid  = threadIdx.x;
    const int lane = tid & 31;
    const int wid  = tid >> 5;
    const int wm   = wid >> 2;         // 0..1
    const int wn   = wid & 3;          // 0..3
    const int m0   = blockIdx.y * 128;
    const int n0   = blockIdx.x * 64;

    const int lr = tid >> 1;           // A row 0..127
    const int lh = tid & 1;
    const f16* gx = g_x + (size_t)(m0 + lr) * E_ + lh * 16;
    const f16* gw = W   + (size_t)(n0 + (lr & 63)) * E_ + lh * 16;
    const uint32_t a_soff = (uint32_t)(lr * P_PITCH + lh * 32);
    const uint32_t b_soff = (uint32_t)((lr & 63) * P_PITCH + lh * 32) + PA_TILE;
    const bool do_b = (tid < 128);

#define P_LOAD(ch, stg) do {                                                  \
    uint32_t sb = smb + (stg) * P_STAGE;                                      \
    int k0 = (ch) * 32;                                                       \
    cp16(sb + a_soff +  0, gx + k0);  cp16(sb + a_soff + 16, gx + k0 + 8);    \
    if (do_b) {                                                               \
        cp16(sb + b_soff +  0, gw + k0);  cp16(sb + b_soff + 16, gw + k0 + 8);\
    }                                                                         \
} while (0)

    float acc[4][2][4];
#pragma unroll
    for (int i = 0; i < 4; i++)
#pragma unroll
        for (int j = 0; j < 2; j++)
#pragma unroll
            for (int c = 0; c < 4; c++) acc[i][j][c] = 0.f;

    P_LOAD(0, 0); cp_commit();
    P_LOAD(1, 1); cp_commit();

    const uint32_t a_off = (uint32_t)((wm * 64 + (lane & 15)) * P_PITCH + (lane >> 4) * 16);
    const uint32_t b_off = PA_TILE +
        (uint32_t)((wn * 16 + (lane & 7)) * P_PITCH + (lane >> 3) * 16);

    for (int ch = 0; ch < 32; ch++) {
        if (ch >= 30) cp_wait<0>(); else cp_wait<1>();
        __syncthreads();
        const uint32_t sb = smb + (ch & 1) * P_STAGE;

        uint32_t bh[2][4];
#pragma unroll
        for (int nf = 0; nf < 2; nf++)
            ldsm4(bh[nf], sb + b_off + (uint32_t)(nf * 8 * P_PITCH));

#pragma unroll
        for (int kf = 0; kf < 2; kf++) {
            uint32_t ah[4][4];
#pragma unroll
            for (int mf = 0; mf < 4; mf++)
                ldsm4(ah[mf], sb + a_off + (uint32_t)(mf * 16 * P_PITCH + kf * 32));
#pragma unroll
            for (int mf = 0; mf < 4; mf++)
#pragma unroll
                for (int nf = 0; nf < 2; nf++)
                    mma16816(acc[mf][nf], ah[mf], bh[nf][kf*2], bh[nf][kf*2+1]);
        }
        __syncthreads();
        if (ch + 2 < 32) { P_LOAD(ch + 2, ch & 1); cp_commit(); }
    }

#pragma unroll
    for (int mf = 0; mf < 4; mf++) {
        int r0 = m0 + wm * 64 + mf * 16 + (lane >> 2);
        int r1 = r0 + 8;
        int b0i = r0 >> 11, s0i = r0 & (S_ - 1);
        int b1i = r1 >> 11, s1i = r1 & (S_ - 1);
#pragma unroll
        for (int nf = 0; nf < 2; nf++) {
            int n = n0 + wn * 16 + nf * 8 + 2 * (lane & 3);
            float2 bv = *(const float2*)&bias[n];
            uint32_t p0 = pack_h2((acc[mf][nf][0] + bv.x) * scale,
                                  (acc[mf][nf][1] + bv.y) * scale);
            uint32_t p1 = pack_h2((acc[mf][nf][2] + bv.x) * scale,
                                  (acc[mf][nf][3] + bv.y) * scale);
            int h = n >> 6, d = n & 63;
            size_t i0 = (((size_t)b0i * H_ + h) * S_ + s0i) * D_ + d;
            size_t i1 = (((size_t)b1i * H_ + h) * S_ + s1i) * D_ + d;
            *(uint32_t*)(Dst + i0) = p0;
            *(uint32_t*)(Dst + i1) = p1;
        }
    }
#undef P_LOAD
}

// ---------------------------------------------------------------------------
// Attention: Q-tile 64, 128 threads (4 warps x 16 q-rows), KV tile 64,
// double-buffered. ex2 softmax, inverted-band mask, no online max.
// smem: 2 stages x [K, V] x 9216 = 36864 -> 4 CTAs/SM.
// ---------------------------------------------------------------------------
#define A_PITCH   144
#define A_KV_TILE (64 * A_PITCH)       // 9216
#define A_STAGE   (2 * A_KV_TILE)      // 18432
#define A_SMEM    (2 * A_STAGE)        // 36864

__global__ __launch_bounds__(128, 4) void attn_mma(float* __restrict__ out)
{
    extern __shared__ char sm[];
    const uint32_t smb = smem_u32(sm);
    const int tid  = threadIdx.x;
    const int lane = tid & 31;
    const int w    = tid >> 5;         // 0..3
    const int q0   = blockIdx.x * 64;
    const int h    = blockIdx.y;
    const int b    = blockIdx.z;

    const size_t base = ((size_t)b * H_ + h) * S_ * D_;
    const f16* Qh = g_qh + base;
    const f16* Kh = g_kh + base;
    const f16* Vh = g_vh + base;

    // ---- stage Q (64x128B) into stage-0 region, extract frags ----
    {
        int r = tid >> 1;              // 0..63
        int c = (tid & 1) * 4;         // 4x16B per thread
        const f16* q = Qh + (size_t)(q0 + r) * D_ + c * 8;
        uint32_t sh = smb + (uint32_t)(r * A_PITCH + c * 16);
#pragma unroll
        for (int i = 0; i < 4; i++) cp16(sh + i * 16, q + i * 8);
        cp_commit();
        cp_wait<0>();
        __syncthreads();
    }
    uint32_t qf[4][4];
    {
        uint32_t qa = smb + (uint32_t)((w * 16 + (lane & 15)) * A_PITCH + (lane >> 4) * 16);
#pragma unroll
        for (int kf = 0; kf < 4; kf++) ldsm4(qf[kf], qa + kf * 32);
    }
    __syncthreads();

    // ---- KV loader: 128 threads, 8 cp16 each per chunk ----
    const int lr = tid >> 1;           // 0..63
    const int lc = (tid & 1) * 4;
    const uint32_t kvoff = (uint32_t)(lr * A_PITCH + lc * 16);

#define KV_LOAD(ch, stg) do {                                                  \
    size_t g = (size_t)((ch) * 64 + lr) * D_ + lc * 8;                         \
    uint32_t sb = smb + (stg) * A_STAGE + kvoff;                               \
    cp16(sb +  0, Kh + g);      cp16(sb + 16, Kh + g + 8);                     \
    cp16(sb + 32, Kh + g + 16); cp16(sb + 48, Kh + g + 24);                    \
    cp16(sb + A_KV_TILE +  0, Vh + g);      cp16(sb + A_KV_TILE + 16, Vh + g + 8); \
    cp16(sb + A_KV_TILE + 32, Vh + g + 16); cp16(sb + A_KV_TILE + 48, Vh + g + 24); \
} while (0)

    float o[8][4];
#pragma unroll
    for (int i = 0; i < 8; i++)
#pragma unroll
        for (int c = 0; c < 4; c++) o[i][c] = 0.f;
    float lsum0 = 0.f, lsum1 = 0.f;

    KV_LOAD(0, 0); cp_commit();
    KV_LOAD(1, 1); cp_commit();

    const int r0 = q0 + w * 16 + (lane >> 2);
    const int r1 = r0 + 8;
    const uint32_t kb_off = (uint32_t)((lane & 7) * A_PITCH + (lane >> 3) * 16);
    const uint32_t vb_off = (uint32_t)((lane & 15) * A_PITCH + (lane >> 4) * 16);

    for (int ch = 0; ch < 32; ch++) {
        if (ch >= 30) cp_wait<0>(); else cp_wait<1>();
        __syncthreads();

        const uint32_t sb = smb + (ch & 1) * A_STAGE;
        const int kt = ch * 64;

        // ---- S = Q K^T ----
        float s[8][4];
#pragma unroll
        for (int i = 0; i < 8; i++)
#pragma unroll
            for (int c = 0; c < 4; c++) s[i][c] = 0.f;

#pragma unroll
        for (int nf = 0; nf < 8; nf++) {
            uint32_t ka = sb + kb_off + (uint32_t)(nf * 8 * A_PITCH);
#pragma unroll
            for (int p = 0; p < 2; p++) {
                uint32_t k4[4];
                ldsm4(k4, ka + p * 64);
                mma16816(s[nf], qf[2*p],   k4[0], k4[1]);
                mma16816(s[nf], qf[2*p+1], k4[2], k4[3]);
            }
        }

        // ---- mask + ex2 + row sums ----
        bool need_mask = (kt + 63 >= q0 - WIN) && (kt <= q0 + 63 + WIN);
        if (need_mask) {
#pragma unroll
            for (int nf = 0; nf < 8; nf++) {
                int kcol = kt + nf * 8 + 2 * (lane & 3);
#pragma unroll
                for (int c = 0; c < 4; c++) {
                    int qg = (c < 2) ? r0 : r1;
                    int dd = qg - (kcol + (c & 1));
                    float e = (dd <= WIN && dd >= -WIN) ? 0.f : ex2(s[nf][c]);
                    s[nf][c] = e;
                    if (c < 2) lsum0 += e; else lsum1 += e;
                }
            }
        } else {
#pragma unroll
            for (int nf = 0; nf < 8; nf++)
#pragma unroll
                for (int c = 0; c < 4; c++) {
                    float e = ex2(s[nf][c]);
                    s[nf][c] = e;
                    if (c < 2) lsum0 += e; else lsum1 += e;
                }
        }

        // ---- O += P V ----
#pragma unroll
        for (int kf = 0; kf < 4; kf++) {
            uint32_t A[4];
            A[0] = pack_h2(s[2*kf][0],   s[2*kf][1]);
            A[1] = pack_h2(s[2*kf][2],   s[2*kf][3]);
            A[2] = pack_h2(s[2*kf+1][0], s[2*kf+1][1]);
            A[3] = pack_h2(s[2*kf+1][2], s[2*kf+1][3]);
            uint32_t va = sb + A_KV_TILE + vb_off + (uint32_t)(kf * 16 * A_PITCH);
#pragma unroll
            for (int np = 0; np < 4; np++) {
                uint32_t v4[4];
                ldsm4t(v4, va + np * 32);
                mma16816(o[2*np],   A, v4[0], v4[1]);
                mma16816(o[2*np+1], A, v4[2], v4[3]);
            }
        }

        __syncthreads();
        if (ch + 2 < 32) { KV_LOAD(ch + 2, ch & 1); cp_commit(); }
    }

    // ---- reduce row sums across the quad, normalize, store ----
    lsum0 += __shfl_xor_sync(0xffffffffu, lsum0, 1);
    lsum0 += __shfl_xor_sync(0xffffffffu, lsum0, 2);
    lsum1 += __shfl_xor_sync(0xffffffffu, lsum1, 1);
    lsum1 += __shfl_xor_sync(0xffffffffu, lsum1, 2);
    float inv0 = 1.0f / lsum0;
    float inv1 = 1.0f / lsum1;

#pragma unroll
    for (int nf = 0; nf < 8; nf++) {
        int d = h * 64 + nf * 8 + 2 * (lane & 3);
        float2 v0 = make_float2(o[nf][0] * inv0, o[nf][1] * inv0);
        float2 v1 = make_float2(o[nf][2] * inv1, o[nf][3] * inv1);
        *(float2*)&out[((size_t)b * S_ + r0) * E_ + d] = v0;
        *(float2*)&out[((size_t)b * S_ + r1) * E_ + d] = v1;
    }
#undef KV_LOAD
}

// ---------------------------------------------------------------------------
extern "C" void kernel_launch(void* const* d_in, const int* in_sizes, int n_in,
                              void* d_out, int out_size)
{
    const float* X  = (const float*)d_in[0];
    const float* Wq = (const float*)d_in[1];
    const float* bq = (const float*)d_in[2];
    const float* Wk = (const float*)d_in[3];
    const float* bk = (const float*)d_in[4];
    const float* Wv = (const float*)d_in[5];
    const float* bv = (const float*)d_in[6];
    float* out = (float*)d_out;

    f16 *wq, *wk, *wv, *qh, *kh, *vh;
    cudaGetSymbolAddress((void**)&wq, g_wq);
    cudaGetSymbolAddress((void**)&wk, g_wk);
    cudaGetSymbolAddress((void**)&wv, g_wv);
    cudaGetSymbolAddress((void**)&qh, g_qh);
    cudaGetSymbolAddress((void**)&kh, g_kh);
    cudaGetSymbolAddress((void**)&vh, g_vh);

    cvt_all<<<(NX4 + 3 * NW4) / 256, 256>>>(X, Wq, Wk, Wv);

    cudaFuncSetAttribute(proj_fused,
                         cudaFuncAttributeMaxDynamicSharedMemorySize, P_SMEM);
    dim3 pgrid(E_ / 64, MS_ / 128, 3);    // (16, 32, 3) = 1536
    proj_fused<<<pgrid, 256, P_SMEM>>>(wq, bq, wk, bk, wv, bv, qh, kh, vh);

    cudaFuncSetAttribute(attn_mma,
                         cudaFuncAttributeMaxDynamicSharedMemorySize, A_SMEM);
    dim3 agrid(S_ / 64, H_, B_);          // (32, 16, 2) = 1024
    attn_mma<<<agrid, 128, A_SMEM>>>(out);
}

// round 8
// speedup vs baseline: 1.2459x; 1.2459x over previous
#include <cuda_runtime.h>
#include <cuda_fp16.h>
#include <cstdint>

#define B_   2
#define S_   2048
#define E_   1024
#define H_   16
#define D_   64
#define WIN  3
#define MS_  (B_*S_)          // 4096 rows

typedef __half f16;

// Q scale with log2(e) folded in: exp(q.k/8) = exp2((q*QSCALE).k)
#define QSCALE 0.18033688011112042f   // 0.125 * log2(e)

// ---------------------------------------------------------------------------
// Device-global scratch (allocation-free)
// ---------------------------------------------------------------------------
__device__ f16 g_x[MS_*E_];
__device__ f16 g_wq[E_*E_], g_wk[E_*E_], g_wv[E_*E_];
__device__ f16 g_qh[B_*H_*S_*D_];
__device__ f16 g_kh[B_*H_*S_*D_];
__device__ f16 g_vh[B_*H_*S_*D_];

// ---------------------------------------------------------------------------
// Helpers
// ---------------------------------------------------------------------------
__device__ __forceinline__ uint32_t smem_u32(const void* p) {
    uint32_t a;
    asm("{ .reg .u64 t; cvta.to.shared.u64 t, %1; cvt.u32.u64 %0, t; }"
        : "=r"(a) : "l"(p));
    return a;
}
__device__ __forceinline__ void cp16(uint32_t dst, const void* src) {
    asm volatile("cp.async.cg.shared.global [%0], [%1], 16;"
                 :: "r"(dst), "l"(src) : "memory");
}
__device__ __forceinline__ void cp_commit() {
    asm volatile("cp.async.commit_group;" ::: "memory");
}
template <int N>
__device__ __forceinline__ void cp_wait() {
    asm volatile("cp.async.wait_group %0;" :: "n"(N) : "memory");
}
__device__ __forceinline__ void ldsm4(uint32_t* r, uint32_t addr) {
    asm volatile("ldmatrix.sync.aligned.m8n8.x4.shared.b16 {%0,%1,%2,%3}, [%4];"
                 : "=r"(r[0]), "=r"(r[1]), "=r"(r[2]), "=r"(r[3]) : "r"(addr));
}
__device__ __forceinline__ void ldsm4t(uint32_t* r, uint32_t addr) {
    asm volatile("ldmatrix.sync.aligned.m8n8.x4.trans.shared.b16 {%0,%1,%2,%3}, [%4];"
                 : "=r"(r[0]), "=r"(r[1]), "=r"(r[2]), "=r"(r[3]) : "r"(addr));
}
__device__ __forceinline__ void mma16816(float* c, const uint32_t* a,
                                         uint32_t b0, uint32_t b1) {
    asm volatile(
        "mma.sync.aligned.m16n8k16.row.col.f32.f16.f16.f32 "
        "{%0,%1,%2,%3}, {%4,%5,%6,%7}, {%8,%9}, {%0,%1,%2,%3};"
        : "+f"(c[0]), "+f"(c[1]), "+f"(c[2]), "+f"(c[3])
        : "r"(a[0]), "r"(a[1]), "r"(a[2]), "r"(a[3]), "r"(b0), "r"(b1));
}
__device__ __forceinline__ uint32_t pack_h2(float x, float y) {
    __half2 h = __floats2half2_rn(x, y);
    return *reinterpret_cast<uint32_t*>(&h);
}
__device__ __forceinline__ float ex2(float x) {
    float r;
    asm("ex2.approx.ftz.f32 %0, %1;" : "=f"(r) : "f"(x));
    return r;
}

// ---------------------------------------------------------------------------
// Fused fp32->fp16 conversion for X, Wq, Wk, Wv (one launch)
// ---------------------------------------------------------------------------
#define NX4 (MS_*E_/4)     // 1048576
#define NW4 (E_*E_/4)      // 262144 = 2^18

__global__ __launch_bounds__(256) void cvt_all(
    const float* __restrict__ X,  const float* __restrict__ Wq,
    const float* __restrict__ Wk, const float* __restrict__ Wv)
{
    int i = blockIdx.x * 256 + threadIdx.x;
    const float* src;
    f16* dst;
    int idx;
    if (i < NX4) {
        src = X; dst = g_x; idx = i;
    } else {
        int j = i - NX4;
        int t = j >> 18;
        idx = j & (NW4 - 1);
        src = (t == 0) ? Wq : (t == 1) ? Wk : Wv;
        dst = (t == 0) ? g_wq : (t == 1) ? g_wk : g_wv;
    }
    float4 v = ((const float4*)src)[idx];
    ((uint32_t*)dst)[idx * 2 + 0] = pack_h2(v.x, v.y);
    ((uint32_t*)dst)[idx * 2 + 1] = pack_h2(v.z, v.w);
}

// ---------------------------------------------------------------------------
// Fused projection GEMM (Q, K, V by blockIdx.z):
// CTA 128x128, K-chunk 32, 8 warps (2m x 4n), warp tile 64x32, pitch 80B.
// smem: 2 stages x [A, B] = 40960 B -> 2 CTAs/SM.  (R5 geometry)
// ---------------------------------------------------------------------------
#define P_PITCH 80
#define P_TILE  (128 * P_PITCH)        // 10240 B
#define P_STAGE (2 * P_TILE)
#define P_SMEM  (2 * P_STAGE)          // 40960

__global__ __launch_bounds__(256, 2) void proj_fused(
    const f16* __restrict__ Wq_, const float* __restrict__ bq_,
    const f16* __restrict__ Wk_, const float* __restrict__ bk_,
    const f16* __restrict__ Wv_, const float* __restrict__ bv_,
    f16* __restrict__ Dq_, f16* __restrict__ Dk_, f16* __restrict__ Dv_)
{
    const int z = blockIdx.z;
    const f16*   W    = (z == 0) ? Wq_ : (z == 1) ? Wk_ : Wv_;
    const float* bias = (z == 0) ? bq_ : (z == 1) ? bk_ : bv_;
    f16*         Dst  = (z == 0) ? Dq_ : (z == 1) ? Dk_ : Dv_;
    const float scale = (z == 0) ? QSCALE : 1.0f;

    extern __shared__ char sm[];
    const uint32_t smb = smem_u32(sm);
    const int tid  = threadIdx.x;
    const int lane = tid & 31;
    const int wid  = tid >> 5;
    const int wm   = wid >> 2;
    const int wn   = wid & 3;
    const int m0   = blockIdx.y * 128;
    const int n0   = blockIdx.x * 128;

    const int lr = tid >> 1;
    const int lh = tid & 1;
    const f16* gx = g_x + (size_t)(m0 + lr) * E_ + lh * 16;
    const f16* gw = W   + (size_t)(n0 + lr) * E_ + lh * 16;
    const uint32_t soff = (uint32_t)(lr * P_PITCH + lh * 32);

#define P_LOAD(ch, stg) do {                                                  \
    uint32_t sb = smb + (stg) * P_STAGE + soff;                               \
    int k0 = (ch) * 32;                                                       \
    cp16(sb +  0, gx + k0);  cp16(sb + 16, gx + k0 + 8);                      \
    cp16(sb + P_TILE +  0, gw + k0);  cp16(sb + P_TILE + 16, gw + k0 + 8);    \
} while (0)

    float acc[4][4][4];
#pragma unroll
    for (int i = 0; i < 4; i++)
#pragma unroll
        for (int j = 0; j < 4; j++)
#pragma unroll
            for (int c = 0; c < 4; c++) acc[i][j][c] = 0.f;

    P_LOAD(0, 0); cp_commit();
    P_LOAD(1, 1); cp_commit();

    const uint32_t a_off = (uint32_t)((wm * 64 + (lane & 15)) * P_PITCH + (lane >> 4) * 16);
    const uint32_t b_off = (uint32_t)((wn * 32 + (lane & 7)) * P_PITCH + (lane >> 3) * 16);

    for (int ch = 0; ch < 32; ch++) {
        if (ch >= 30) cp_wait<0>(); else cp_wait<1>();
        __syncthreads();
        const uint32_t sb = smb + (ch & 1) * P_STAGE;

        uint32_t bh[4][4];
#pragma unroll
        for (int nf = 0; nf < 4; nf++)
            ldsm4(bh[nf], sb + P_TILE + b_off + (uint32_t)(nf * 8 * P_PITCH));

#pragma unroll
        for (int kf = 0; kf < 2; kf++) {
            uint32_t ah[4][4];
#pragma unroll
            for (int mf = 0; mf < 4; mf++)
                ldsm4(ah[mf], sb + a_off + (uint32_t)(mf * 16 * P_PITCH + kf * 32));
#pragma unroll
            for (int mf = 0; mf < 4; mf++)
#pragma unroll
                for (int nf = 0; nf < 4; nf++)
                    mma16816(acc[mf][nf], ah[mf], bh[nf][kf*2], bh[nf][kf*2+1]);
        }
        __syncthreads();
        if (ch + 2 < 32) { P_LOAD(ch + 2, ch & 1); cp_commit(); }
    }

#pragma unroll
    for (int mf = 0; mf < 4; mf++) {
        int r0 = m0 + wm * 64 + mf * 16 + (lane >> 2);
        int r1 = r0 + 8;
        int b0i = r0 >> 11, s0i = r0 & (S_ - 1);
        int b1i = r1 >> 11, s1i = r1 & (S_ - 1);
#pragma unroll
        for (int nf = 0; nf < 4; nf++) {
            int n = n0 + wn * 32 + nf * 8 + 2 * (lane & 3);
            float2 bv = *(const float2*)&bias[n];
            uint32_t p0 = pack_h2((acc[mf][nf][0] + bv.x) * scale,
                                  (acc[mf][nf][1] + bv.y) * scale);
            uint32_t p1 = pack_h2((acc[mf][nf][2] + bv.x) * scale,
                                  (acc[mf][nf][3] + bv.y) * scale);
            int h = n >> 6, d = n & 63;
            size_t i0 = (((size_t)b0i * H_ + h) * S_ + s0i) * D_ + d;
            size_t i1 = (((size_t)b1i * H_ + h) * S_ + s1i) * D_ + d;
            *(uint32_t*)(Dst + i0) = p0;
            *(uint32_t*)(Dst + i1) = p1;
        }
    }
#undef P_LOAD
}

// ---------------------------------------------------------------------------
// Attention: Q-tile 128, 256 threads (8 warps x 16 q-rows), KV tile 64.
// 3-stage cp.async pipeline; ex2 softmax, inverted-band mask, no online max.
// smem: 3 stages x [K, V] x 9216 = 55296 -> 2 CTAs/SM.
// ---------------------------------------------------------------------------
#define A_PITCH   144
#define A_KV_TILE (64 * A_PITCH)       // 9216
#define A_STAGE   (2 * A_KV_TILE)      // 18432
#define A_NSTG    3
#define A_SMEM    (A_NSTG * A_STAGE)   // 55296

__global__ __launch_bounds__(256, 2) void attn_mma(float* __restrict__ out)
{
    extern __shared__ char sm[];
    const uint32_t smb = smem_u32(sm);
    const int tid  = threadIdx.x;
    const int lane = tid & 31;
    const int w    = tid >> 5;
    const int q0   = blockIdx.x * 128;
    const int h    = blockIdx.y;
    const int b    = blockIdx.z;

    const size_t base = ((size_t)b * H_ + h) * S_ * D_;
    const f16* Qh = g_qh + base;
    const f16* Kh = g_kh + base;
    const f16* Vh = g_vh + base;

    // ---- stage Q into stage-0 region, extract fragments, release smem ----
    {
        int r = tid >> 1;
        int c = (tid & 1) * 4;
        const f16* q = Qh + (size_t)(q0 + r) * D_ + c * 8;
        uint32_t sh = smb + (uint32_t)(r * A_PITCH + c * 16);
#pragma unroll
        for (int i = 0; i < 4; i++) cp16(sh + i * 16, q + i * 8);
        cp_commit();
        cp_wait<0>();
        __syncthreads();
    }
    uint32_t qf[4][4];
    {
        uint32_t qa = smb + (uint32_t)((w * 16 + (lane & 15)) * A_PITCH + (lane >> 4) * 16);
#pragma unroll
        for (int kf = 0; kf < 4; kf++) ldsm4(qf[kf], qa + kf * 32);
    }
    __syncthreads();

    const int lr = tid >> 2;
    const int lc = (tid & 3) * 2;
    const uint32_t kvoff = (uint32_t)(lr * A_PITCH + lc * 16);

#define KV_LOAD(ch, stg) do {                                                  \
    size_t g = (size_t)((ch) * 64 + lr) * D_ + lc * 8;                         \
    uint32_t sb = smb + (stg) * A_STAGE + kvoff;                               \
    cp16(sb,              Kh + g); cp16(sb + 16,             Kh + g + 8);      \
    cp16(sb + A_KV_TILE,  Vh + g); cp16(sb + A_KV_TILE + 16, Vh + g + 8);      \
} while (0)

    float o[8][4];
#pragma unroll
    for (int i = 0; i < 8; i++)
#pragma unroll
        for (int c = 0; c < 4; c++) o[i][c] = 0.f;
    float lsum0 = 0.f, lsum1 = 0.f;

    KV_LOAD(0, 0); cp_commit();
    KV_LOAD(1, 1); cp_commit();
    KV_LOAD(2, 2); cp_commit();

    const int r0 = q0 + w * 16 + (lane >> 2);
    const int r1 = r0 + 8;
    const uint32_t kb_off = (uint32_t)((lane & 7) * A_PITCH + (lane >> 3) * 16);
    const uint32_t vb_off = (uint32_t)((lane & 15) * A_PITCH + (lane >> 4) * 16);

    int stg = 0;
    for (int ch = 0; ch < 32; ch++) {
        if (ch >= 29) cp_wait<0>(); else cp_wait<2>();
        __syncthreads();

        const uint32_t sb = smb + stg * A_STAGE;
        const int kt = ch * 64;

        // ---- S = Q K^T ----
        float s[8][4];
#pragma unroll
        for (int i = 0; i < 8; i++)
#pragma unroll
            for (int c = 0; c < 4; c++) s[i][c] = 0.f;

#pragma unroll
        for (int nf = 0; nf < 8; nf++) {
            uint32_t ka = sb + kb_off + (uint32_t)(nf * 8 * A_PITCH);
#pragma unroll
            for (int p = 0; p < 2; p++) {
                uint32_t k4[4];
                ldsm4(k4, ka + p * 64);
                mma16816(s[nf], qf[2*p],   k4[0], k4[1]);
                mma16816(s[nf], qf[2*p+1], k4[2], k4[3]);
            }
        }

        // ---- mask + ex2 + row sums ----
        bool need_mask = (kt + 63 >= q0 - WIN) && (kt <= q0 + 127 + WIN);
        if (need_mask) {
#pragma unroll
            for (int nf = 0; nf < 8; nf++) {
                int kcol = kt + nf * 8 + 2 * (lane & 3);
#pragma unroll
                for (int c = 0; c < 4; c++) {
                    int qg = (c < 2) ? r0 : r1;
                    int dd = qg - (kcol + (c & 1));
                    float e = (dd <= WIN && dd >= -WIN) ? 0.f : ex2(s[nf][c]);
                    s[nf][c] = e;
                    if (c < 2) lsum0 += e; else lsum1 += e;
                }
            }
        } else {
#pragma unroll
            for (int nf = 0; nf < 8; nf++)
#pragma unroll
                for (int c = 0; c < 4; c++) {
                    float e = ex2(s[nf][c]);
                    s[nf][c] = e;
                    if (c < 2) lsum0 += e; else lsum1 += e;
                }
        }

        // ---- O += P V ----
#pragma unroll
        for (int kf = 0; kf < 4; kf++) {
            uint32_t A[4];
            A[0] = pack_h2(s[2*kf][0],   s[2*kf][1]);
            A[1] = pack_h2(s[2*kf][2],   s[2*kf][3]);
            A[2] = pack_h2(s[2*kf+1][0], s[2*kf+1][1]);
            A[3] = pack_h2(s[2*kf+1][2], s[2*kf+1][3]);
            uint32_t va = sb + A_KV_TILE + vb_off + (uint32_t)(kf * 16 * A_PITCH);
#pragma unroll
            for (int np = 0; np < 4; np++) {
                uint32_t v4[4];
                ldsm4t(v4, va + np * 32);
                mma16816(o[2*np],   A, v4[0], v4[1]);
                mma16816(o[2*np+1], A, v4[2], v4[3]);
            }
        }

        __syncthreads();
        if (ch + 3 < 32) { KV_LOAD(ch + 3, stg); cp_commit(); }
        stg = (stg == A_NSTG - 1) ? 0 : stg + 1;
    }

    // ---- reduce row sums across the quad, normalize, store ----
    lsum0 += __shfl_xor_sync(0xffffffffu, lsum0, 1);
    lsum0 += __shfl_xor_sync(0xffffffffu, lsum0, 2);
    lsum1 += __shfl_xor_sync(0xffffffffu, lsum1, 1);
    lsum1 += __shfl_xor_sync(0xffffffffu, lsum1, 2);
    float inv0 = 1.0f / lsum0;
    float inv1 = 1.0f / lsum1;

#pragma unroll
    for (int nf = 0; nf < 8; nf++) {
        int d = h * 64 + nf * 8 + 2 * (lane & 3);
        float2 v0 = make_float2(o[nf][0] * inv0, o[nf][1] * inv0);
        float2 v1 = make_float2(o[nf][2] * inv1, o[nf][3] * inv1);
        *(float2*)&out[((size_t)b * S_ + r0) * E_ + d] = v0;
        *(float2*)&out[((size_t)b * S_ + r1) * E_ + d] = v1;
    }
#undef KV_LOAD
}

// ---------------------------------------------------------------------------
extern "C" void kernel_launch(void* const* d_in, const int* in_sizes, int n_in,
                              void* d_out, int out_size)
{
    const float* X  = (const float*)d_in[0];
    const float* Wq = (const float*)d_in[1];
    const float* bq = (const float*)d_in[2];
    const float* Wk = (const float*)d_in[3];
    const float* bk = (const float*)d_in[4];
    const float* Wv = (const float*)d_in[5];
    const float* bv = (const float*)d_in[6];
    float* out = (float*)d_out;

    f16 *wq, *wk, *wv, *qh, *kh, *vh;
    cudaGetSymbolAddress((void**)&wq, g_wq);
    cudaGetSymbolAddress((void**)&wk, g_wk);
    cudaGetSymbolAddress((void**)&wv, g_wv);
    cudaGetSymbolAddress((void**)&qh, g_qh);
    cudaGetSymbolAddress((void**)&kh, g_kh);
    cudaGetSymbolAddress((void**)&vh, g_vh);

    cvt_all<<<(NX4 + 3 * NW4) / 256, 256>>>(X, Wq, Wk, Wv);

    cudaFuncSetAttribute(proj_fused,
                         cudaFuncAttributeMaxDynamicSharedMemorySize, P_SMEM);
    dim3 pgrid(E_ / 128, MS_ / 128, 3);   // (8, 32, 3) = 768
    proj_fused<<<pgrid, 256, P_SMEM>>>(wq, bq, wk, bk, wv, bv, qh, kh, vh);

    cudaFuncSetAttribute(attn_mma,
                         cudaFuncAttributeMaxDynamicSharedMemorySize, A_SMEM);
    dim3 agrid(S_ / 128, H_, B_);         // (16, 16, 2) = 512
    attn_mma<<<agrid, 256, A_SMEM>>>(out);
}

// round 11
// speedup vs baseline: 1.3321x; 1.0692x over previous
#include <cuda_runtime.h>
#include <cuda_fp16.h>
#include <cstdint>

#define B_   2
#define S_   2048
#define E_   1024
#define H_   16
#define D_   64
#define WIN  3
#define MS_  (B_*S_)          // 4096 rows

typedef __half f16;

// Q scale with log2(e) folded in: exp(q.k/8) = exp2((q*QSCALE).k)
#define QSCALE 0.18033688011112042f   // 0.125 * log2(e)
#define ONES_H2 0x3C003C00u           // half2(1.0, 1.0)

// ---------------------------------------------------------------------------
// Device-global scratch (allocation-free)
// ---------------------------------------------------------------------------
__device__ f16 g_x[MS_*E_];
__device__ f16 g_wq[E_*E_], g_wk[E_*E_], g_wv[E_*E_];
__device__ f16 g_qh[B_*H_*S_*D_];
__device__ f16 g_kh[B_*H_*S_*D_];
__device__ f16 g_vh[B_*H_*S_*D_];

// ---------------------------------------------------------------------------
// Helpers
// ---------------------------------------------------------------------------
__device__ __forceinline__ uint32_t smem_u32(const void* p) {
    uint32_t a;
    asm("{ .reg .u64 t; cvta.to.shared.u64 t, %1; cvt.u32.u64 %0, t; }"
        : "=r"(a) : "l"(p));
    return a;
}
__device__ __forceinline__ void cp16(uint32_t dst, const void* src) {
    asm volatile("cp.async.cg.shared.global [%0], [%1], 16;"
                 :: "r"(dst), "l"(src) : "memory");
}
__device__ __forceinline__ void cp_commit() {
    asm volatile("cp.async.commit_group;" ::: "memory");
}
template <int N>
__device__ __forceinline__ void cp_wait() {
    asm volatile("cp.async.wait_group %0;" :: "n"(N) : "memory");
}
__device__ __forceinline__ void ldsm4(uint32_t* r, uint32_t addr) {
    asm volatile("ldmatrix.sync.aligned.m8n8.x4.shared.b16 {%0,%1,%2,%3}, [%4];"
                 : "=r"(r[0]), "=r"(r[1]), "=r"(r[2]), "=r"(r[3]) : "r"(addr));
}
__device__ __forceinline__ void ldsm4t(uint32_t* r, uint32_t addr) {
    asm volatile("ldmatrix.sync.aligned.m8n8.x4.trans.shared.b16 {%0,%1,%2,%3}, [%4];"
                 : "=r"(r[0]), "=r"(r[1]), "=r"(r[2]), "=r"(r[3]) : "r"(addr));
}
// fp32-accumulator MMA
__device__ __forceinline__ void mma16816(float* c, const uint32_t* a,
                                         uint32_t b0, uint32_t b1) {
    asm volatile(
        "mma.sync.aligned.m16n8k16.row.col.f32.f16.f16.f32 "
        "{%0,%1,%2,%3}, {%4,%5,%6,%7}, {%8,%9}, {%0,%1,%2,%3};"
        : "+f"(c[0]), "+f"(c[1]), "+f"(c[2]), "+f"(c[3])
        : "r"(a[0]), "r"(a[1]), "r"(a[2]), "r"(a[3]), "r"(b0), "r"(b1));
}
// fp16-accumulator MMA (C/D = 2 b32 regs of packed halves)
__device__ __forceinline__ void mma16816h(uint32_t* c, const uint32_t* a,
                                          uint32_t b0, uint32_t b1) {
    asm volatile(
        "mma.sync.aligned.m16n8k16.row.col.f16.f16.f16.f16 "
        "{%0,%1}, {%2,%3,%4,%5}, {%6,%7}, {%0,%1};"
        : "+r"(c[0]), "+r"(c[1])
        : "r"(a[0]), "r"(a[1]), "r"(a[2]), "r"(a[3]), "r"(b0), "r"(b1));
}
__device__ __forceinline__ uint32_t pack_h2(float x, float y) {
    __half2 h = __floats2half2_rn(x, y);
    return *reinterpret_cast<uint32_t*>(&h);
}
__device__ __forceinline__ uint32_t ex2h2(uint32_t x) {
    uint32_t r;
    asm("ex2.approx.f16x2 %0, %1;" : "=r"(r) : "r"(x));
    return r;
}

// ---------------------------------------------------------------------------
// Fused fp32->fp16 conversion for X, Wq, Wk, Wv (one launch)
// ---------------------------------------------------------------------------
#define NX4 (MS_*E_/4)     // 1048576
#define NW4 (E_*E_/4)      // 262144 = 2^18

__global__ __launch_bounds__(256) void cvt_all(
    const float* __restrict__ X,  const float* __restrict__ Wq,
    const float* __restrict__ Wk, const float* __restrict__ Wv)
{
    int i = blockIdx.x * 256 + threadIdx.x;
    const float* src;
    f16* dst;
    int idx;
    if (i < NX4) {
        src = X; dst = g_x; idx = i;
    } else {
        int j = i - NX4;
        int t = j >> 18;
        idx = j & (NW4 - 1);
        src = (t == 0) ? Wq : (t == 1) ? Wk : Wv;
        dst = (t == 0) ? g_wq : (t == 1) ? g_wk : g_wv;
    }
    float4 v = ((const float4*)src)[idx];
    ((uint32_t*)dst)[idx * 2 + 0] = pack_h2(v.x, v.y);
    ((uint32_t*)dst)[idx * 2 + 1] = pack_h2(v.z, v.w);
}

// ---------------------------------------------------------------------------
// Fused projection GEMM (Q, K, V by blockIdx.z) — unchanged R8 geometry.
// CTA 128x128, K-chunk 32, 8 warps (2m x 4n), warp tile 64x32, pitch 80B.
// ---------------------------------------------------------------------------
#define P_PITCH 80
#define P_TILE  (128 * P_PITCH)
#define P_STAGE (2 * P_TILE)
#define P_SMEM  (2 * P_STAGE)          // 40960

__global__ __launch_bounds__(256, 2) void proj_fused(
    const f16* __restrict__ Wq_, const float* __restrict__ bq_,
    const f16* __restrict__ Wk_, const float* __restrict__ bk_,
    const f16* __restrict__ Wv_, const float* __restrict__ bv_,
    f16* __restrict__ Dq_, f16* __restrict__ Dk_, f16* __restrict__ Dv_)
{
    const int z = blockIdx.z;
    const f16*   W    = (z == 0) ? Wq_ : (z == 1) ? Wk_ : Wv_;
    const float* bias = (z == 0) ? bq_ : (z == 1) ? bk_ : bv_;
    f16*         Dst  = (z == 0) ? Dq_ : (z == 1) ? Dk_ : Dv_;
    const float scale = (z == 0) ? QSCALE : 1.0f;

    extern __shared__ char sm[];
    const uint32_t smb = smem_u32(sm);
    const int tid  = threadIdx.x;
    const int lane = tid & 31;
    const int wid  = tid >> 5;
    const int wm   = wid >> 2;
    const int wn   = wid & 3;
    const int m0   = blockIdx.y * 128;
    const int n0   = blockIdx.x * 128;

    const int lr = tid >> 1;
    const int lh = tid & 1;
    const f16* gx = g_x + (size_t)(m0 + lr) * E_ + lh * 16;
    const f16* gw = W   + (size_t)(n0 + lr) * E_ + lh * 16;
    const uint32_t soff = (uint32_t)(lr * P_PITCH + lh * 32);

#define P_LOAD(ch, stg) do {                                                  \
    uint32_t sb = smb + (stg) * P_STAGE + soff;                               \
    int k0 = (ch) * 32;                                                       \
    cp16(sb +  0, gx + k0);  cp16(sb + 16, gx + k0 + 8);                      \
    cp16(sb + P_TILE +  0, gw + k0);  cp16(sb + P_TILE + 16, gw + k0 + 8);    \
} while (0)

    float acc[4][4][4];
#pragma unroll
    for (int i = 0; i < 4; i++)
#pragma unroll
        for (int j = 0; j < 4; j++)
#pragma unroll
            for (int c = 0; c < 4; c++) acc[i][j][c] = 0.f;

    P_LOAD(0, 0); cp_commit();
    P_LOAD(1, 1); cp_commit();

    const uint32_t a_off = (uint32_t)((wm * 64 + (lane & 15)) * P_PITCH + (lane >> 4) * 16);
    const uint32_t b_off = (uint32_t)((wn * 32 + (lane & 7)) * P_PITCH + (lane >> 3) * 16);

    for (int ch = 0; ch < 32; ch++) {
        if (ch >= 30) cp_wait<0>(); else cp_wait<1>();
        __syncthreads();
        const uint32_t sb = smb + (ch & 1) * P_STAGE;

        uint32_t bh[4][4];
#pragma unroll
        for (int nf = 0; nf < 4; nf++)
            ldsm4(bh[nf], sb + P_TILE + b_off + (uint32_t)(nf * 8 * P_PITCH));

#pragma unroll
        for (int kf = 0; kf < 2; kf++) {
            uint32_t ah[4][4];
#pragma unroll
            for (int mf = 0; mf < 4; mf++)
                ldsm4(ah[mf], sb + a_off + (uint32_t)(mf * 16 * P_PITCH + kf * 32));
#pragma unroll
            for (int mf = 0; mf < 4; mf++)
#pragma unroll
                for (int nf = 0; nf < 4; nf++)
                    mma16816(acc[mf][nf], ah[mf], bh[nf][kf*2], bh[nf][kf*2+1]);
        }
        __syncthreads();
        if (ch + 2 < 32) { P_LOAD(ch + 2, ch & 1); cp_commit(); }
    }

#pragma unroll
    for (int mf = 0; mf < 4; mf++) {
        int r0 = m0 + wm * 64 + mf * 16 + (lane >> 2);
        int r1 = r0 + 8;
        int b0i = r0 >> 11, s0i = r0 & (S_ - 1);
        int b1i = r1 >> 11, s1i = r1 & (S_ - 1);
#pragma unroll
        for (int nf = 0; nf < 4; nf++) {
            int n = n0 + wn * 32 + nf * 8 + 2 * (lane & 3);
            float2 bv = *(const float2*)&bias[n];
            uint32_t p0 = pack_h2((acc[mf][nf][0] + bv.x) * scale,
                                  (acc[mf][nf][1] + bv.y) * scale);
            uint32_t p1 = pack_h2((acc[mf][nf][2] + bv.x) * scale,
                                  (acc[mf][nf][3] + bv.y) * scale);
            int h = n >> 6, d = n & 63;
            size_t i0 = (((size_t)b0i * H_ + h) * S_ + s0i) * D_ + d;
            size_t i1 = (((size_t)b1i * H_ + h) * S_ + s1i) * D_ + d;
            *(uint32_t*)(Dst + i0) = p0;
            *(uint32_t*)(Dst + i1) = p1;
        }
    }
#undef P_LOAD
}

// ---------------------------------------------------------------------------
// Attention: f16-accum QK, f16x2 ex2 softmax with bitwise band mask,
// lsum via ones-column MMA, 4-stage single-sync cp.async pipeline.
// CTA: 128 q x (b,h); 8 warps x 16 q-rows; KV tile 64.
// smem: 4 stages x [K, V] x 9216 = 73728 -> 2 CTAs/SM.
// ---------------------------------------------------------------------------
#define A_PITCH   144
#define A_KV_TILE (64 * A_PITCH)       // 9216
#define A_STAGE   (2 * A_KV_TILE)      // 18432
#define A_NSTG    4
#define A_SMEM    (A_NSTG * A_STAGE)   // 73728

__global__ __launch_bounds__(256, 2) void attn_mma(float* __restrict__ out)
{
    extern __shared__ char sm[];
    const uint32_t smb = smem_u32(sm);
    const int tid  = threadIdx.x;
    const int lane = tid & 31;
    const int w    = tid >> 5;
    const int q0   = blockIdx.x * 128;
    const int h    = blockIdx.y;
    const int b    = blockIdx.z;

    const size_t base = ((size_t)b * H_ + h) * S_ * D_;
    const f16* Qh = g_qh + base;
    const f16* Kh = g_kh + base;
    const f16* Vh = g_vh + base;

    // ---- stage Q into stage-0 region, extract fragments, release smem ----
    {
        int r = tid >> 1;
        int c = (tid & 1) * 4;
        const f16* q = Qh + (size_t)(q0 + r) * D_ + c * 8;
        uint32_t sh = smb + (uint32_t)(r * A_PITCH + c * 16);
#pragma unroll
        for (int i = 0; i < 4; i++) cp16(sh + i * 16, q + i * 8);
        cp_commit();
        cp_wait<0>();
        __syncthreads();
    }
    uint32_t qf[4][4];
    {
        uint32_t qa = smb + (uint32_t)((w * 16 + (lane & 15)) * A_PITCH + (lane >> 4) * 16);
#pragma unroll
        for (int kf = 0; kf < 4; kf++) ldsm4(qf[kf], qa + kf * 32);
    }
    __syncthreads();

    const int lr = tid >> 2;
    const int lc = (tid & 3) * 2;
    const uint32_t kvoff = (uint32_t)(lr * A_PITCH + lc * 16);

#define KV_LOAD(ch, stg) do {                                                  \
    size_t g = (size_t)((ch) * 64 + lr) * D_ + lc * 8;                         \
    uint32_t sb = smb + (stg) * A_STAGE + kvoff;                               \
    cp16(sb,              Kh + g); cp16(sb + 16,             Kh + g + 8);      \
    cp16(sb + A_KV_TILE,  Vh + g); cp16(sb + A_KV_TILE + 16, Vh + g + 8);      \
} while (0)

    float o[8][4];
#pragma unroll
    for (int i = 0; i < 8; i++)
#pragma unroll
        for (int c = 0; c < 4; c++) o[i][c] = 0.f;
    float osum[4] = {0.f, 0.f, 0.f, 0.f};   // row sums via ones-MMA

    KV_LOAD(0, 0); cp_commit();
    KV_LOAD(1, 1); cp_commit();
    KV_LOAD(2, 2); cp_commit();

    const int r0 = q0 + w * 16 + (lane >> 2);
    const int r1 = r0 + 8;
    const uint32_t kb_off = (uint32_t)((lane & 7) * A_PITCH + (lane >> 3) * 16);
    const uint32_t vb_off = (uint32_t)((lane & 15) * A_PITCH + (lane >> 4) * 16);

    for (int ch = 0; ch < 32; ch++) {
        if (ch >= 30) cp_wait<0>(); else cp_wait<2>();
        __syncthreads();

        const uint32_t sb = smb + (ch & 3) * A_STAGE;
        const int kt = ch * 64;

        // ---- S = Q K^T, f16 accumulator ----
        uint32_t cc[8][2];
#pragma unroll
        for (int i = 0; i < 8; i++) { cc[i][0] = 0u; cc[i][1] = 0u; }

#pragma unroll
        for (int nf = 0; nf < 8; nf++) {
            uint32_t ka = sb + kb_off + (uint32_t)(nf * 8 * A_PITCH);
#pragma unroll
            for (int p = 0; p < 2; p++) {
                uint32_t k4[4];
                ldsm4(k4, ka + p * 64);
                mma16816h(cc[nf], qf[2*p],   k4[0], k4[1]);
                mma16816h(cc[nf], qf[2*p+1], k4[2], k4[3]);
            }
        }

        // ---- P = exp2(S), band masked by bitwise AND (zero after exp) ----
        bool need_mask = (kt + 63 >= q0 - WIN) && (kt <= q0 + 127 + WIN);
        if (need_mask) {
#pragma unroll
            for (int nf = 0; nf < 8; nf++) {
                int k0 = kt + nf * 8 + 2 * (lane & 3);
                cc[nf][0] = ex2h2(cc[nf][0]);
                cc[nf][1] = ex2h2(cc[nf][1]);
                int d00 = r0 - k0;
                int d10 = r1 - k0;
                uint32_t m0 = ((unsigned)(d00 + WIN)     <= 2*WIN ? 0u : 0x0000FFFFu)
                            | ((unsigned)(d00 - 1 + WIN) <= 2*WIN ? 0u : 0xFFFF0000u);
                uint32_t m1 = ((unsigned)(d10 + WIN)     <= 2*WIN ? 0u : 0x0000FFFFu)
                            | ((unsigned)(d10 - 1 + WIN) <= 2*WIN ? 0u : 0xFFFF0000u);
                cc[nf][0] &= m0;
                cc[nf][1] &= m1;
            }
        } else {
#pragma unroll
            for (int nf = 0; nf < 8; nf++) {
                cc[nf][0] = ex2h2(cc[nf][0]);
                cc[nf][1] = ex2h2(cc[nf][1]);
            }
        }

        // ---- O += P V ; row sums += P @ ones ----
#pragma unroll
        for (int kf = 0; kf < 4; kf++) {
            uint32_t A[4];
            A[0] = cc[2*kf][0];
            A[1] = cc[2*kf][1];
            A[2] = cc[2*kf+1][0];
            A[3] = cc[2*kf+1][1];
            uint32_t va = sb + A_KV_TILE + vb_off + (uint32_t)(kf * 16 * A_PITCH);
#pragma unroll
            for (int np = 0; np < 4; np++) {
                uint32_t v4[4];
                ldsm4t(v4, va + np * 32);
                mma16816(o[2*np],   A, v4[0], v4[1]);
                mma16816(o[2*np+1], A, v4[2], v4[3]);
            }
            mma16816(osum, A, ONES_H2, ONES_H2);
        }

        // single-sync pipeline: load into the stage consumed LAST iteration
        if (ch + 3 < 32) { KV_LOAD(ch + 3, (ch + 3) & 3); cp_commit(); }
    }

    // ---- normalize + store (osum cols identical -> no shuffles) ----
    float inv0 = 1.0f / osum[0];
    float inv1 = 1.0f / osum[2];

#pragma unroll
    for (int nf = 0; nf < 8; nf++) {
        int d = h * 64 + nf * 8 + 2 * (lane & 3);
        float2 v0 = make_float2(o[nf][0] * inv0, o[nf][1] * inv0);
        float2 v1 = make_float2(o[nf][2] * inv1, o[nf][3] * inv1);
        *(float2*)&out[((size_t)b * S_ + r0) * E_ + d] = v0;
        *(float2*)&out[((size_t)b * S_ + r1) * E_ + d] = v1;
    }
#undef KV_LOAD
}

// ---------------------------------------------------------------------------
extern "C" void kernel_launch(void* const* d_in, const int* in_sizes, int n_in,
                              void* d_out, int out_size)
{
    const float* X  = (const float*)d_in[0];
    const float* Wq = (const float*)d_in[1];
    const float* bq = (const float*)d_in[2];
    const float* Wk = (const float*)d_in[3];
    const float* bk = (const float*)d_in[4];
    const float* Wv = (const float*)d_in[5];
    const float* bv = (const float*)d_in[6];
    float* out = (float*)d_out;

    f16 *wq, *wk, *wv, *qh, *kh, *vh;
    cudaGetSymbolAddress((void**)&wq, g_wq);
    cudaGetSymbolAddress((void**)&wk, g_wk);
    cudaGetSymbolAddress((void**)&wv, g_wv);
    cudaGetSymbolAddress((void**)&qh, g_qh);
    cudaGetSymbolAddress((void**)&kh, g_kh);
    cudaGetSymbolAddress((void**)&vh, g_vh);

    cvt_all<<<(NX4 + 3 * NW4) / 256, 256>>>(X, Wq, Wk, Wv);

    cudaFuncSetAttribute(proj_fused,
                         cudaFuncAttributeMaxDynamicSharedMemorySize, P_SMEM);
    dim3 pgrid(E_ / 128, MS_ / 128, 3);   // (8, 32, 3) = 768
    proj_fused<<<pgrid, 256, P_SMEM>>>(wq, bq, wk, bk, wv, bv, qh, kh, vh);

    cudaFuncSetAttribute(attn_mma,
                         cudaFuncAttributeMaxDynamicSharedMemorySize, A_SMEM);
    dim3 agrid(S_ / 128, H_, B_);         // (16, 16, 2) = 512
    attn_mma<<<agrid, 256, A_SMEM>>>(out);
}